// round 10
// baseline (speedup 1.0000x reference)
#include <cuda_runtime.h>

typedef unsigned long long ull;

#define NIN   784
#define DD    10
#define WW    4
#define NOUT  10
#define NL    3
#define NC    49            // 784/16 k-chunks
#define BMAX  131072

// __device__ scratch (no allocation)
__device__ float4 Wt5_g[NC * 5 * 32];         // Win {w(k),w(k+1)} pairs, lane-interleaved
__device__ float  dwp_g[NL * 16 * DD * 12];   // data_w, e padded 10->12
__device__ float  acts0_g[(size_t)BMAX * 40]; // phase-1 output

__global__ void prep_kernel(const float* __restrict__ Win,
                            const float* __restrict__ dw)
{
    int i = blockIdx.x * blockDim.x + threadIdx.x;
    if (i < NC * 5 * 32) {
        int lane = i & 31;
        int p    = (i >> 5) % 5;
        int c    = i / 160;
        int og   = lane & 7;
        int ks   = lane >> 3;
        // slots idx=2p, 2p+1; idx = kp*5 + j
        int i0 = 2 * p, i1 = 2 * p + 1;
        int k0 = c * 16 + ks * 4 + (i0 / 5) * 2, j0 = i0 % 5;
        int k1 = c * 16 + ks * 4 + (i1 / 5) * 2, j1 = i1 % 5;
        Wt5_g[i] = make_float4(Win[(og * 5 + j0) * NIN + k0],
                               Win[(og * 5 + j0) * NIN + k0 + 1],
                               Win[(og * 5 + j1) * NIN + k1],
                               Win[(og * 5 + j1) * NIN + k1 + 1]);
    }
    if (i < NL * 16 * DD * 12) {
        int e = i % 12;
        int r = i / 12;
        dwp_g[i] = (e < DD) ? dw[r * DD + e] : 0.0f;
    }
}

__device__ __forceinline__ void ffma2(ull &d, ull a, ull b) {
    asm("fma.rn.f32x2 %0, %1, %2, %0;" : "+l"(d) : "l"(a), "l"(b));
}
__device__ __forceinline__ ull pack2(float lo, float hi) {
    ull r; asm("mov.b64 %0, {%1, %2};" : "=l"(r) : "f"(lo), "f"(hi)); return r;
}
__device__ __forceinline__ void unpack2(ull v, float &lo, float &hi) {
    asm("mov.b64 {%0, %1}, %2;" : "=f"(lo), "=f"(hi) : "l"(v));
}

// ============================================================================
// Kernel A: acts0 = relu(x @ Win^T + b_in)
// Warp owns 4 rows; lane = (ks 0..3, og 0..7); accumulators k-paired f32x2
// (even-k / odd-k partial sums) -> x float4 loads ARE the packed operands.
// 128-thread blocks, 5 blocks/SM for latency hiding.  No barriers.
// ============================================================================
__global__ void __launch_bounds__(128, 5)
phase1_kernel(const float* __restrict__ x,
              const float* __restrict__ bin,
              int B)
{
    const int tid  = threadIdx.x;
    const int warp = tid >> 5;
    const int lane = tid & 31;
    const int og   = lane & 7;
    const int ks   = lane >> 3;

    const int row0 = blockIdx.x * 16 + warp * 4;
    const float* xr = x + (size_t)row0 * NIN + ks * 4;

    ull acc[4][5];
    #pragma unroll
    for (int r = 0; r < 4; ++r)
        #pragma unroll
        for (int j = 0; j < 5; ++j) acc[r][j] = 0ull;

    const ulonglong2* wbase = (const ulonglong2*)Wt5_g + lane;

    #pragma unroll 1
    for (int c = 0; c < NC; ++c) {
        // W: 5 coalesced LDG.128 -> 10 {w,w'} k-pairs (this lane's ks,og slice)
        ulonglong2 wv0 = __ldg(wbase + (c * 5 + 0) * 32);
        ulonglong2 wv1 = __ldg(wbase + (c * 5 + 1) * 32);
        ulonglong2 wv2 = __ldg(wbase + (c * 5 + 2) * 32);
        ulonglong2 wv3 = __ldg(wbase + (c * 5 + 3) * 32);
        ulonglong2 wv4 = __ldg(wbase + (c * 5 + 4) * 32);
        ull wk0[5] = {wv0.x, wv0.y, wv1.x, wv1.y, wv2.x};  // pairs (k,k+1)
        ull wk1[5] = {wv2.y, wv3.x, wv3.y, wv4.x, wv4.y};  // pairs (k+2,k+3)

        // x: 4 rows, this lane's 4-k strip; each LDG.128 touches 1 line
        #pragma unroll
        for (int r = 0; r < 4; ++r) {
            float4 xv = __ldg((const float4*)(xr + r * NIN + c * 16));
            ulonglong2 xu = *(ulonglong2*)&xv;   // bit-reinterpret: 2 k-pairs
            #pragma unroll
            for (int j = 0; j < 5; ++j) {
                ffma2(acc[r][j], xu.x, wk0[j]);
                ffma2(acc[r][j], xu.y, wk1[j]);
            }
        }
    }

    // reduce across ks strips (lanes differing in bits 3,4)
    #pragma unroll
    for (int r = 0; r < 4; ++r)
        #pragma unroll
        for (int j = 0; j < 5; ++j) {
            float lo, hi, olo, ohi;
            unpack2(acc[r][j], lo, hi);
            olo = __shfl_xor_sync(0xffffffffu, lo, 8);
            ohi = __shfl_xor_sync(0xffffffffu, hi, 8);
            lo += olo; hi += ohi;
            olo = __shfl_xor_sync(0xffffffffu, lo, 16);
            ohi = __shfl_xor_sync(0xffffffffu, hi, 16);
            lo += olo; hi += ohi;
            acc[r][j] = pack2(lo, hi);
        }

    // lane (ks,og) writes row row0+ks, cols og*5..og*5+4 (fold even+odd sums)
    {
        float* dst = acts0_g + (size_t)(row0 + ks) * 40 + og * 5;
        #pragma unroll
        for (int j = 0; j < 5; ++j) {
            float lo, hi; unpack2(acc[ks][j], lo, hi);
            float b = __ldg(bin + og * 5 + j);
            dst[j] = fmaxf(lo + hi + b, 0.0f);
        }
    }
}

// ============================================================================
// Kernel B: routed layers + output banks (unchanged, known-good).
// ============================================================================
__global__ void __launch_bounds__(256, 2)
phase2_kernel(const float* __restrict__ gw,
              const float* __restrict__ db,
              const float* __restrict__ wout,
              float* __restrict__ out,
              int B)
{
    __shared__ __align__(16) float gws[NL * 16 * DD];
    __shared__ __align__(16) float dbs[NL * 16 * DD];
    __shared__ __align__(16) float wouts[WW * NOUT * DD];

    const int tid = threadIdx.x;
    for (int i = tid; i < NL * 16 * DD; i += 256) { gws[i] = gw[i]; dbs[i] = db[i]; }
    for (int i = tid; i < WW * NOUT * DD; i += 256) wouts[i] = wout[i];
    __syncthreads();

    const size_t row = (size_t)blockIdx.x * 256 + tid;

    float a[WW][DD];
    {
        const float4* ap = (const float4*)(acts0_g + row * 40);
        #pragma unroll
        for (int i = 0; i < 10; ++i) {
            float4 v = __ldg(ap + i);
            int o = i * 4;
            a[o / DD][o % DD]         = v.x;
            a[(o+1) / DD][(o+1) % DD] = v.y;
            a[(o+2) / DD][(o+2) % DD] = v.z;
            a[(o+3) / DD][(o+3) % DD] = v.w;
        }
    }

    float tg = 0.0f;

    #pragma unroll 1
    for (int l = 0; l < NL; ++l) {
        const float* gwl = gws + l * 160;
        const float* dbl = dbs + l * 160;
        const float* dwl = dwp_g + l * 16 * 120;

        ull nxt[WW][5];
        #pragma unroll
        for (int t = 0; t < WW; ++t)
            #pragma unroll
            for (int j = 0; j < 5; ++j) nxt[t][j] = 0ull;

        #pragma unroll
        for (int s = 0; s < WW; ++s) {
            ull a2[DD];
            #pragma unroll
            for (int d = 0; d < DD; ++d) a2[d] = pack2(a[s][d], a[s][d]);

            #pragma unroll
            for (int t = 0; t < WW; ++t) {
                const int edge = s * WW + t;

                const float* gv = gwl + edge * DD;
                float g = 0.0f;
                #pragma unroll
                for (int d = 0; d < DD; ++d) g += a[s][d] * gv[d];
                g = fminf(fmaxf(g, 0.0f), 1.0f);
                tg += g;
                ull g2 = pack2(g, g);

                ull m[5];
                const ull* bv = (const ull*)(dbl + edge * DD);
                #pragma unroll
                for (int j = 0; j < 5; ++j) m[j] = bv[j];

                const float* drow = dwl + edge * 120;
                #pragma unroll
                for (int din = 0; din < DD; ++din) {
                    const char* rp = (const char*)(drow + din * 12);
                    ulonglong2 wA = __ldg((const ulonglong2*)rp);
                    ulonglong2 wB = __ldg((const ulonglong2*)(rp + 16));
                    ull        wC = __ldg((const ull*)(rp + 32));
                    ull ad = a2[din];
                    ffma2(m[0], ad, wA.x);
                    ffma2(m[1], ad, wA.y);
                    ffma2(m[2], ad, wB.x);
                    ffma2(m[3], ad, wB.y);
                    ffma2(m[4], ad, wC);
                }

                #pragma unroll
                for (int j = 0; j < 5; ++j) ffma2(nxt[t][j], g2, m[j]);
            }
        }

        #pragma unroll
        for (int t = 0; t < WW; ++t)
            #pragma unroll
            for (int j = 0; j < 5; ++j) {
                float lo, hi; unpack2(nxt[t][j], lo, hi);
                a[t][2 * j]     = fmaxf(lo, 0.0f);
                a[t][2 * j + 1] = fmaxf(hi, 0.0f);
            }
    }

    float ov[NOUT];
    #pragma unroll
    for (int c = 0; c < NOUT; ++c) {
        float o = 0.0f;
        #pragma unroll
        for (int w = 0; w < WW; ++w)
            #pragma unroll
            for (int d = 0; d < DD; ++d)
                o += a[w][d] * wouts[(w * NOUT + c) * DD + d];
        ov[c] = o;
    }
    float2* op = (float2*)(out + row * NOUT);
    #pragma unroll
    for (int j = 0; j < 5; ++j) op[j] = make_float2(ov[2 * j], ov[2 * j + 1]);
    out[(size_t)B * NOUT + row] = tg;
}

extern "C" void kernel_launch(void* const* d_in, const int* in_sizes, int n_in,
                              void* d_out, int out_size)
{
    const float* x    = (const float*)d_in[0];
    const float* Win  = (const float*)d_in[1];
    const float* bin  = (const float*)d_in[2];
    const float* gw   = (const float*)d_in[3];
    const float* dw   = (const float*)d_in[4];
    const float* db   = (const float*)d_in[5];
    const float* wout = (const float*)d_in[6];

    const int B = in_sizes[0] / NIN;

    prep_kernel<<<(NC * 5 * 32 + 255) / 256, 256>>>(Win, dw);
    phase1_kernel<<<B / 16, 128>>>(x, bin, B);
    phase2_kernel<<<B / 256, 256>>>(gw, db, wout, (float*)d_out, B);
}

// round 12
// speedup vs baseline: 2.1702x; 2.1702x over previous
#include <cuda_runtime.h>
#include <cuda_bf16.h>
#include <cstdint>

typedef unsigned long long ull;

#define NIN  784
#define DD   10
#define WW   4
#define NOUT 10
#define NL   3
#define NKC  49            // 784/16 k16 chunks
#define BMAX 131072

// ---- __device__ scratch (no allocation) ----
__device__ __align__(16) uint4 Bfrag_g[NKC][5][32];   // B fragments: {r0h,r1h,r0l,r1l}
__device__ float dwp_g[NL * 16 * DD * 12];
__device__ float acts0_g[(size_t)BMAX * 40];

__global__ void prep_kernel(const float* __restrict__ Win,
                            const float* __restrict__ dw)
{
    int i = blockIdx.x * 256 + threadIdx.x;
    if (i < NKC * 5 * 32) {
        int lane = i & 31;
        int t    = (i >> 5) % 5;
        int c    = i / 160;
        int n    = t * 8 + (lane >> 2);          // output index 0..39
        int k0   = c * 16 + (lane & 3) * 2;      // k, k+1, k+8, k+9 all < 784
        float v0 = Win[n * NIN + k0];
        float v1 = Win[n * NIN + k0 + 1];
        float v2 = Win[n * NIN + k0 + 8];
        float v3 = Win[n * NIN + k0 + 9];
        __nv_bfloat16 h0 = __float2bfloat16(v0), h1 = __float2bfloat16(v1);
        __nv_bfloat16 h2 = __float2bfloat16(v2), h3 = __float2bfloat16(v3);
        __nv_bfloat16 l0 = __float2bfloat16(v0 - __bfloat162float(h0));
        __nv_bfloat16 l1 = __float2bfloat16(v1 - __bfloat162float(h1));
        __nv_bfloat16 l2 = __float2bfloat16(v2 - __bfloat162float(h2));
        __nv_bfloat16 l3 = __float2bfloat16(v3 - __bfloat162float(h3));
        uint4 r;
        r.x = ((uint32_t)__bfloat16_as_ushort(h1) << 16) | __bfloat16_as_ushort(h0);
        r.y = ((uint32_t)__bfloat16_as_ushort(h3) << 16) | __bfloat16_as_ushort(h2);
        r.z = ((uint32_t)__bfloat16_as_ushort(l1) << 16) | __bfloat16_as_ushort(l0);
        r.w = ((uint32_t)__bfloat16_as_ushort(l3) << 16) | __bfloat16_as_ushort(l2);
        Bfrag_g[c][t][lane] = r;
    }
    if (i < NL * 16 * DD * 12) {
        int e = i % 12;
        int r = i / 12;
        dwp_g[i] = (e < DD) ? dw[r * DD + e] : 0.0f;
    }
}

// ---------- helpers ----------
__device__ __forceinline__ void cvt_hilo(float2 v, uint32_t &h, uint32_t &l) {
    asm("cvt.rn.bf16x2.f32 %0, %1, %2;" : "=r"(h) : "f"(v.y), "f"(v.x));
    float h0 = __uint_as_float(h << 16);
    float h1 = __uint_as_float(h & 0xffff0000u);
    float r0 = v.x - h0, r1 = v.y - h1;
    asm("cvt.rn.bf16x2.f32 %0, %1, %2;" : "=r"(l) : "f"(r1), "f"(r0));
}
__device__ __forceinline__ void mma16816(float* d, const uint32_t* a,
                                         uint32_t b0, uint32_t b1) {
    asm volatile(
        "mma.sync.aligned.m16n8k16.row.col.f32.bf16.bf16.f32 "
        "{%0,%1,%2,%3}, {%4,%5,%6,%7}, {%8,%9}, {%0,%1,%2,%3};"
        : "+f"(d[0]), "+f"(d[1]), "+f"(d[2]), "+f"(d[3])
        : "r"(a[0]), "r"(a[1]), "r"(a[2]), "r"(a[3]), "r"(b0), "r"(b1));
}
__device__ __forceinline__ void ffma2(ull &d, ull a, ull b) {
    asm("fma.rn.f32x2 %0, %1, %2, %0;" : "+l"(d) : "l"(a), "l"(b));
}
__device__ __forceinline__ ull pack2(float lo, float hi) {
    ull r; asm("mov.b64 %0, {%1, %2};" : "=l"(r) : "f"(lo), "f"(hi)); return r;
}
__device__ __forceinline__ void unpack2(ull v, float &lo, float &hi) {
    asm("mov.b64 {%0, %1}, %2;" : "=f"(lo), "=f"(hi) : "l"(v));
}

// ============================================================================
// Phase 1: acts0 = relu(x @ Win^T + b_in) via mma.sync bf16 3-pass hi/lo.
// Warp = 32 rows (2 m16 tiles) x 40 outputs (5 n8 tiles).  No smem, no bars.
// ============================================================================
__global__ void __launch_bounds__(256, 2)
phase1_mma(const float* __restrict__ x,
           const float* __restrict__ bin,
           int B)
{
    const int tid  = threadIdx.x;
    const int warp = tid >> 5;
    const int lane = tid & 31;
    const int qr   = lane >> 2;        // fragment row within m16
    const int qc   = (lane & 3) * 2;   // fragment k-pair base

    const int row0 = (blockIdx.x * 8 + warp) * 32;
    const float* xr = x + (size_t)row0 * NIN;

    float acc[2][5][4];
    #pragma unroll
    for (int mt = 0; mt < 2; ++mt)
        #pragma unroll
        for (int t = 0; t < 5; ++t)
            #pragma unroll
            for (int q = 0; q < 4; ++q) acc[mt][t][q] = 0.0f;

    #pragma unroll 1
    for (int c = 0; c < NKC; ++c) {
        const int k0 = c * 16 + qc;

        // B fragments: 5 coalesced LDG.128 (hi pair + lo pair per n-tile)
        uint32_t bh[5][2], bl[5][2];
        #pragma unroll
        for (int t = 0; t < 5; ++t) {
            uint4 bv = __ldg(&Bfrag_g[c][t][lane]);
            bh[t][0] = bv.x; bh[t][1] = bv.y;
            bl[t][0] = bv.z; bl[t][1] = bv.w;
        }

        // A fragments from global x, converted to bf16 hi/lo in registers
        uint32_t ah[2][4], al[2][4];
        #pragma unroll
        for (int mt = 0; mt < 2; ++mt) {
            const float* pr = xr + (size_t)(mt * 16 + qr) * NIN;
            float2 xa0 = *(const float2*)(pr + k0);
            float2 xb0 = *(const float2*)(pr + 8 * NIN + k0);
            float2 xa1 = *(const float2*)(pr + k0 + 8);
            float2 xb1 = *(const float2*)(pr + 8 * NIN + k0 + 8);
            cvt_hilo(xa0, ah[mt][0], al[mt][0]);
            cvt_hilo(xb0, ah[mt][1], al[mt][1]);
            cvt_hilo(xa1, ah[mt][2], al[mt][2]);
            cvt_hilo(xb1, ah[mt][3], al[mt][3]);
        }

        // 3-pass MMA ladder: hi*hi + lo*hi + hi*lo
        #pragma unroll
        for (int mt = 0; mt < 2; ++mt)
            #pragma unroll
            for (int t = 0; t < 5; ++t) {
                mma16816(acc[mt][t], ah[mt], bh[t][0], bh[t][1]);
                mma16816(acc[mt][t], al[mt], bh[t][0], bh[t][1]);
                mma16816(acc[mt][t], ah[mt], bl[t][0], bl[t][1]);
            }
    }

    // epilogue: D fragment rows (qr, qr+8), cols (qc, qc+1) per n-tile
    #pragma unroll
    for (int mt = 0; mt < 2; ++mt) {
        const size_t ra = (size_t)row0 + mt * 16 + qr;
        #pragma unroll
        for (int t = 0; t < 5; ++t) {
            const int cc = t * 8 + qc;
            float b0 = __ldg(bin + cc), b1 = __ldg(bin + cc + 1);
            float2 v0, v1;
            v0.x = fmaxf(acc[mt][t][0] + b0, 0.0f);
            v0.y = fmaxf(acc[mt][t][1] + b1, 0.0f);
            v1.x = fmaxf(acc[mt][t][2] + b0, 0.0f);
            v1.y = fmaxf(acc[mt][t][3] + b1, 0.0f);
            *(float2*)(acts0_g + ra * 40 + cc)       = v0;
            *(float2*)(acts0_g + (ra + 8) * 40 + cc) = v1;
        }
    }
}

// ============================================================================
// Phase 2: routed layers + output banks (known-good from R8)
// ============================================================================
__global__ void __launch_bounds__(256, 2)
phase2_kernel(const float* __restrict__ gw,
              const float* __restrict__ db,
              const float* __restrict__ wout,
              float* __restrict__ out,
              int B)
{
    __shared__ __align__(16) float gws[NL * 16 * DD];
    __shared__ __align__(16) float dbs[NL * 16 * DD];
    __shared__ __align__(16) float wouts[WW * NOUT * DD];

    const int tid = threadIdx.x;
    for (int i = tid; i < NL * 16 * DD; i += 256) { gws[i] = gw[i]; dbs[i] = db[i]; }
    for (int i = tid; i < WW * NOUT * DD; i += 256) wouts[i] = wout[i];
    __syncthreads();

    const size_t row = (size_t)blockIdx.x * 256 + tid;

    float a[WW][DD];
    {
        const float4* ap = (const float4*)(acts0_g + row * 40);
        #pragma unroll
        for (int i = 0; i < 10; ++i) {
            float4 v = __ldg(ap + i);
            int o = i * 4;
            a[o / DD][o % DD]         = v.x;
            a[(o+1) / DD][(o+1) % DD] = v.y;
            a[(o+2) / DD][(o+2) % DD] = v.z;
            a[(o+3) / DD][(o+3) % DD] = v.w;
        }
    }

    float tg = 0.0f;

    #pragma unroll 1
    for (int l = 0; l < NL; ++l) {
        const float* gwl = gws + l * 160;
        const float* dbl = dbs + l * 160;
        const float* dwl = dwp_g + l * 16 * 120;

        ull nxt[WW][5];
        #pragma unroll
        for (int t = 0; t < WW; ++t)
            #pragma unroll
            for (int j = 0; j < 5; ++j) nxt[t][j] = 0ull;

        #pragma unroll
        for (int s = 0; s < WW; ++s) {
            ull a2[DD];
            #pragma unroll
            for (int d = 0; d < DD; ++d) a2[d] = pack2(a[s][d], a[s][d]);

            #pragma unroll
            for (int t = 0; t < WW; ++t) {
                const int edge = s * WW + t;

                const float* gv = gwl + edge * DD;
                float g = 0.0f;
                #pragma unroll
                for (int d = 0; d < DD; ++d) g += a[s][d] * gv[d];
                g = fminf(fmaxf(g, 0.0f), 1.0f);
                tg += g;
                ull g2 = pack2(g, g);

                ull m[5];
                const ull* bv = (const ull*)(dbl + edge * DD);
                #pragma unroll
                for (int j = 0; j < 5; ++j) m[j] = bv[j];

                const float* drow = dwl + edge * 120;
                #pragma unroll
                for (int din = 0; din < DD; ++din) {
                    const char* rp = (const char*)(drow + din * 12);
                    ulonglong2 wA = __ldg((const ulonglong2*)rp);
                    ulonglong2 wB = __ldg((const ulonglong2*)(rp + 16));
                    ull        wC = __ldg((const ull*)(rp + 32));
                    ull ad = a2[din];
                    ffma2(m[0], ad, wA.x);
                    ffma2(m[1], ad, wA.y);
                    ffma2(m[2], ad, wB.x);
                    ffma2(m[3], ad, wB.y);
                    ffma2(m[4], ad, wC);
                }

                #pragma unroll
                for (int j = 0; j < 5; ++j) ffma2(nxt[t][j], g2, m[j]);
            }
        }

        #pragma unroll
        for (int t = 0; t < WW; ++t)
            #pragma unroll
            for (int j = 0; j < 5; ++j) {
                float lo, hi; unpack2(nxt[t][j], lo, hi);
                a[t][2 * j]     = fmaxf(lo, 0.0f);
                a[t][2 * j + 1] = fmaxf(hi, 0.0f);
            }
    }

    float ov[NOUT];
    #pragma unroll
    for (int c = 0; c < NOUT; ++c) {
        float o = 0.0f;
        #pragma unroll
        for (int w = 0; w < WW; ++w)
            #pragma unroll
            for (int d = 0; d < DD; ++d)
                o += a[w][d] * wouts[(w * NOUT + c) * DD + d];
        ov[c] = o;
    }
    float2* op = (float2*)(out + row * NOUT);
    #pragma unroll
    for (int j = 0; j < 5; ++j) op[j] = make_float2(ov[2 * j], ov[2 * j + 1]);
    out[(size_t)B * NOUT + row] = tg;
}

extern "C" void kernel_launch(void* const* d_in, const int* in_sizes, int n_in,
                              void* d_out, int out_size)
{
    const float* x    = (const float*)d_in[0];
    const float* Win  = (const float*)d_in[1];
    const float* bin  = (const float*)d_in[2];
    const float* gw   = (const float*)d_in[3];
    const float* dw   = (const float*)d_in[4];
    const float* db   = (const float*)d_in[5];
    const float* wout = (const float*)d_in[6];

    const int B = in_sizes[0] / NIN;

    prep_kernel<<<(NKC * 5 * 32 + 255) / 256, 256>>>(Win, dw);
    phase1_mma<<<B / 256, 256>>>(x, bin, B);
    phase2_kernel<<<B / 256, 256>>>(gw, db, wout, (float*)d_out, B);
}

// round 14
// speedup vs baseline: 2.3007x; 1.0601x over previous
#include <cuda_runtime.h>
#include <cuda_bf16.h>
#include <cstdint>

typedef unsigned long long ull;

#define NIN  784
#define DD   10
#define WW   4
#define NOUT 10
#define NL   3
#define NKC  49            // 784/16 k16 chunks
#define ASTR 44            // acts smem row stride (floats): 16B-aligned, conflict-free

// ---- dynamic smem layout (floats) ----
#define SM_ACTS   0                       // 256*44 = 11264 f
#define SM_GWS    (256 * ASTR)            // 480 f
#define SM_DBS    (SM_GWS + 480)          // 480 f
#define SM_WOUTS  (SM_DBS + 480)          // 400 f
#define SM_TOTF   (SM_WOUTS + 400)        // 12624 floats = 50496 B

// ---- __device__ scratch (no allocation) ----
__device__ __align__(16) uint4 Bfrag_g[NKC][5][32];   // B fragments: {r0h,r1h,r0l,r1l}
__device__ float dwp_g[NL * 16 * DD * 12];

__global__ void prep_kernel(const float* __restrict__ Win,
                            const float* __restrict__ dw)
{
    int i = blockIdx.x * 256 + threadIdx.x;
    if (i < NKC * 5 * 32) {
        int lane = i & 31;
        int t    = (i >> 5) % 5;
        int c    = i / 160;
        int n    = t * 8 + (lane >> 2);
        int k0   = c * 16 + (lane & 3) * 2;
        float v0 = Win[n * NIN + k0];
        float v1 = Win[n * NIN + k0 + 1];
        float v2 = Win[n * NIN + k0 + 8];
        float v3 = Win[n * NIN + k0 + 9];
        __nv_bfloat16 h0 = __float2bfloat16(v0), h1 = __float2bfloat16(v1);
        __nv_bfloat16 h2 = __float2bfloat16(v2), h3 = __float2bfloat16(v3);
        __nv_bfloat16 l0 = __float2bfloat16(v0 - __bfloat162float(h0));
        __nv_bfloat16 l1 = __float2bfloat16(v1 - __bfloat162float(h1));
        __nv_bfloat16 l2 = __float2bfloat16(v2 - __bfloat162float(h2));
        __nv_bfloat16 l3 = __float2bfloat16(v3 - __bfloat162float(h3));
        uint4 r;
        r.x = ((uint32_t)__bfloat16_as_ushort(h1) << 16) | __bfloat16_as_ushort(h0);
        r.y = ((uint32_t)__bfloat16_as_ushort(h3) << 16) | __bfloat16_as_ushort(h2);
        r.z = ((uint32_t)__bfloat16_as_ushort(l1) << 16) | __bfloat16_as_ushort(l0);
        r.w = ((uint32_t)__bfloat16_as_ushort(l3) << 16) | __bfloat16_as_ushort(l2);
        Bfrag_g[c][t][lane] = r;
    }
    if (i < NL * 16 * DD * 12) {
        int e = i % 12;
        int r = i / 12;
        dwp_g[i] = (e < DD) ? dw[r * DD + e] : 0.0f;
    }
}

// ---------- helpers ----------
__device__ __forceinline__ void cvt_hilo(float2 v, uint32_t &h, uint32_t &l) {
    asm("cvt.rn.bf16x2.f32 %0, %1, %2;" : "=r"(h) : "f"(v.y), "f"(v.x));
    float h0 = __uint_as_float(h << 16);
    float h1 = __uint_as_float(h & 0xffff0000u);
    float r0 = v.x - h0, r1 = v.y - h1;
    asm("cvt.rn.bf16x2.f32 %0, %1, %2;" : "=r"(l) : "f"(r1), "f"(r0));
}
__device__ __forceinline__ void mma16816(float* d, const uint32_t* a,
                                         uint32_t b0, uint32_t b1) {
    asm volatile(
        "mma.sync.aligned.m16n8k16.row.col.f32.bf16.bf16.f32 "
        "{%0,%1,%2,%3}, {%4,%5,%6,%7}, {%8,%9}, {%0,%1,%2,%3};"
        : "+f"(d[0]), "+f"(d[1]), "+f"(d[2]), "+f"(d[3])
        : "r"(a[0]), "r"(a[1]), "r"(a[2]), "r"(a[3]), "r"(b0), "r"(b1));
}
__device__ __forceinline__ void ffma2(ull &d, ull a, ull b) {
    asm("fma.rn.f32x2 %0, %1, %2, %0;" : "+l"(d) : "l"(a), "l"(b));
}
__device__ __forceinline__ ull pack2(float lo, float hi) {
    ull r; asm("mov.b64 %0, {%1, %2};" : "=l"(r) : "f"(lo), "f"(hi)); return r;
}
__device__ __forceinline__ void unpack2(ull v, float &lo, float &hi) {
    asm("mov.b64 {%0, %1}, %2;" : "=f"(lo), "=f"(hi) : "l"(v));
}

// ============================================================================
// Fused kernel: phase 1 (mma.sync bf16 3-pass hi/lo GEMM) -> smem acts ->
// phase 2 (routed layers, 1 row/thread) -> out.  Block = 256 rows.
// ============================================================================
__global__ void __launch_bounds__(256, 2)
routenet_fused(const float* __restrict__ x,
               const float* __restrict__ bin,
               const float* __restrict__ gw,
               const float* __restrict__ db,
               const float* __restrict__ wout,
               float* __restrict__ out,
               int B)
{
    extern __shared__ __align__(16) float smf[];
    float* acts  = smf + SM_ACTS;
    float* gws   = smf + SM_GWS;
    float* dbs   = smf + SM_DBS;
    float* wouts = smf + SM_WOUTS;

    const int tid  = threadIdx.x;
    const int warp = tid >> 5;
    const int lane = tid & 31;
    const int qr   = lane >> 2;
    const int qc   = (lane & 3) * 2;

    for (int i = tid; i < NL * 16 * DD; i += 256) { gws[i] = gw[i]; dbs[i] = db[i]; }
    for (int i = tid; i < WW * NOUT * DD; i += 256) wouts[i] = wout[i];

    // =====================================================================
    // Phase 1: warp covers 32 rows (2 m16 tiles) x 40 outputs (5 n8 tiles)
    // =====================================================================
    const int row0 = blockIdx.x * 256 + warp * 32;
    const float* xr = x + (size_t)row0 * NIN;

    float acc[2][5][4];
    #pragma unroll
    for (int mt = 0; mt < 2; ++mt)
        #pragma unroll
        for (int t = 0; t < 5; ++t)
            #pragma unroll
            for (int q = 0; q < 4; ++q) acc[mt][t][q] = 0.0f;

    #pragma unroll 1
    for (int c = 0; c < NKC; ++c) {
        const int k0 = c * 16 + qc;

        uint32_t bh[5][2], bl[5][2];
        #pragma unroll
        for (int t = 0; t < 5; ++t) {
            uint4 bv = __ldg(&Bfrag_g[c][t][lane]);
            bh[t][0] = bv.x; bh[t][1] = bv.y;
            bl[t][0] = bv.z; bl[t][1] = bv.w;
        }

        uint32_t ah[2][4], al[2][4];
        #pragma unroll
        for (int mt = 0; mt < 2; ++mt) {
            const float* pr = xr + (size_t)(mt * 16 + qr) * NIN;
            float2 xa0 = *(const float2*)(pr + k0);
            float2 xb0 = *(const float2*)(pr + 8 * NIN + k0);
            float2 xa1 = *(const float2*)(pr + k0 + 8);
            float2 xb1 = *(const float2*)(pr + 8 * NIN + k0 + 8);
            cvt_hilo(xa0, ah[mt][0], al[mt][0]);
            cvt_hilo(xb0, ah[mt][1], al[mt][1]);
            cvt_hilo(xa1, ah[mt][2], al[mt][2]);
            cvt_hilo(xb1, ah[mt][3], al[mt][3]);
        }

        #pragma unroll
        for (int mt = 0; mt < 2; ++mt)
            #pragma unroll
            for (int t = 0; t < 5; ++t) {
                mma16816(acc[mt][t], ah[mt], bh[t][0], bh[t][1]);
                mma16816(acc[mt][t], al[mt], bh[t][0], bh[t][1]);
                mma16816(acc[mt][t], ah[mt], bl[t][0], bl[t][1]);
            }
    }

    // epilogue -> smem acts (block-local rows, stride ASTR)
    #pragma unroll
    for (int mt = 0; mt < 2; ++mt) {
        const int sra = warp * 32 + mt * 16 + qr;
        #pragma unroll
        for (int t = 0; t < 5; ++t) {
            const int cc = t * 8 + qc;
            float b0 = __ldg(bin + cc), b1 = __ldg(bin + cc + 1);
            float2 v0, v1;
            v0.x = fmaxf(acc[mt][t][0] + b0, 0.0f);
            v0.y = fmaxf(acc[mt][t][1] + b1, 0.0f);
            v1.x = fmaxf(acc[mt][t][2] + b0, 0.0f);
            v1.y = fmaxf(acc[mt][t][3] + b1, 0.0f);
            *(float2*)(acts + sra * ASTR + cc)       = v0;
            *(float2*)(acts + (sra + 8) * ASTR + cc) = v1;
        }
    }
    __syncthreads();

    // =====================================================================
    // Phase 2: one row per thread (row = blockIdx*256 + tid)
    // =====================================================================
    float a[WW][DD];
    {
        const float4* ap = (const float4*)(acts + tid * ASTR);
        #pragma unroll
        for (int i = 0; i < 10; ++i) {
            float4 v = ap[i];
            int o = i * 4;
            a[o / DD][o % DD]         = v.x;
            a[(o+1) / DD][(o+1) % DD] = v.y;
            a[(o+2) / DD][(o+2) % DD] = v.z;
            a[(o+3) / DD][(o+3) % DD] = v.w;
        }
    }

    float tg = 0.0f;

    #pragma unroll 1
    for (int l = 0; l < NL; ++l) {
        const float* gwl = gws + l * 160;
        const float* dbl = dbs + l * 160;
        const float* dwl = dwp_g + l * 16 * 120;

        ull nxt[WW][5];
        #pragma unroll
        for (int t = 0; t < WW; ++t)
            #pragma unroll
            for (int j = 0; j < 5; ++j) nxt[t][j] = 0ull;

        #pragma unroll
        for (int s = 0; s < WW; ++s) {
            ull a2[DD];
            #pragma unroll
            for (int d = 0; d < DD; ++d) a2[d] = pack2(a[s][d], a[s][d]);

            #pragma unroll
            for (int t = 0; t < WW; ++t) {
                const int edge = s * WW + t;

                const float* gv = gwl + edge * DD;
                float g = 0.0f;
                #pragma unroll
                for (int d = 0; d < DD; ++d) g += a[s][d] * gv[d];
                g = fminf(fmaxf(g, 0.0f), 1.0f);
                tg += g;
                ull g2 = pack2(g, g);

                ull m[5];
                const ull* bv = (const ull*)(dbl + edge * DD);
                #pragma unroll
                for (int j = 0; j < 5; ++j) m[j] = bv[j];

                const float* drow = dwl + edge * 120;
                #pragma unroll
                for (int din = 0; din < DD; ++din) {
                    const char* rp = (const char*)(drow + din * 12);
                    ulonglong2 wA = __ldg((const ulonglong2*)rp);
                    ulonglong2 wB = __ldg((const ulonglong2*)(rp + 16));
                    ull        wC = __ldg((const ull*)(rp + 32));
                    ull ad = a2[din];
                    ffma2(m[0], ad, wA.x);
                    ffma2(m[1], ad, wA.y);
                    ffma2(m[2], ad, wB.x);
                    ffma2(m[3], ad, wB.y);
                    ffma2(m[4], ad, wC);
                }

                #pragma unroll
                for (int j = 0; j < 5; ++j) ffma2(nxt[t][j], g2, m[j]);
            }
        }

        #pragma unroll
        for (int t = 0; t < WW; ++t)
            #pragma unroll
            for (int j = 0; j < 5; ++j) {
                float lo, hi; unpack2(nxt[t][j], lo, hi);
                a[t][2 * j]     = fmaxf(lo, 0.0f);
                a[t][2 * j + 1] = fmaxf(hi, 0.0f);
            }
    }

    // output banks + total_gate
    const size_t grow = (size_t)blockIdx.x * 256 + tid;
    float ov[NOUT];
    #pragma unroll
    for (int c = 0; c < NOUT; ++c) {
        float o = 0.0f;
        #pragma unroll
        for (int w = 0; w < WW; ++w)
            #pragma unroll
            for (int d = 0; d < DD; ++d)
                o += a[w][d] * wouts[(w * NOUT + c) * DD + d];
        ov[c] = o;
    }
    float2* op = (float2*)(out + grow * NOUT);
    #pragma unroll
    for (int j = 0; j < 5; ++j) op[j] = make_float2(ov[2 * j], ov[2 * j + 1]);
    out[(size_t)B * NOUT + grow] = tg;
}

extern "C" void kernel_launch(void* const* d_in, const int* in_sizes, int n_in,
                              void* d_out, int out_size)
{
    const float* x    = (const float*)d_in[0];
    const float* Win  = (const float*)d_in[1];
    const float* bin  = (const float*)d_in[2];
    const float* gw   = (const float*)d_in[3];
    const float* dw   = (const float*)d_in[4];
    const float* db   = (const float*)d_in[5];
    const float* wout = (const float*)d_in[6];

    const int B = in_sizes[0] / NIN;
    const int smem_bytes = SM_TOTF * 4;

    cudaFuncSetAttribute(routenet_fused,
                         cudaFuncAttributeMaxDynamicSharedMemorySize,
                         smem_bytes);

    prep_kernel<<<(NKC * 5 * 32 + 255) / 256, 256>>>(Win, dw);
    routenet_fused<<<B / 256, 256, smem_bytes>>>(x, bin, gw, db, wout,
                                                 (float*)d_out, B);
}

// round 15
// speedup vs baseline: 2.3265x; 1.0112x over previous
#include <cuda_runtime.h>
#include <cuda_bf16.h>
#include <cstdint>

typedef unsigned long long ull;

#define NIN  784
#define DD   10
#define WW   4
#define NOUT 10
#define NL   3
#define NKC  49            // 784/16 k16 chunks
#define ASTR 44            // acts smem row stride (floats)

// ---- dynamic smem layout (floats) ----
#define SM_ACTS   0                       // 256*44 = 11264 f
#define SM_GWS    (256 * ASTR)            // 480 f
#define SM_DBS    (SM_GWS + 480)          // 480 f
#define SM_WOUTS  (SM_DBS + 480)          // 400 f
#define SM_TOTF   (SM_WOUTS + 400)        // 12624 floats = 50496 B

// ---- __device__ scratch (no allocation) ----
// B fragments under the k-permutation slot(2qc,2qc+1,2qc+8,2qc+9) -> phys 4qc..4qc+3
__device__ __align__(16) uint4 Bfrag_g[NKC][5][32];   // {b0h,b1h,b0l,b1l}
__device__ float dwp_g[NL * 16 * DD * 12];

__global__ void prep_kernel(const float* __restrict__ Win,
                            const float* __restrict__ dw)
{
    int i = blockIdx.x * 256 + threadIdx.x;
    if (i < NKC * 5 * 32) {
        int lane = i & 31;
        int t    = (i >> 5) % 5;
        int c    = i / 160;
        int n    = t * 8 + (lane >> 2);
        int k0   = c * 16 + (lane & 3) * 4;       // contiguous float4 of k
        float v0 = Win[n * NIN + k0];
        float v1 = Win[n * NIN + k0 + 1];
        float v2 = Win[n * NIN + k0 + 2];
        float v3 = Win[n * NIN + k0 + 3];
        __nv_bfloat16 h0 = __float2bfloat16(v0), h1 = __float2bfloat16(v1);
        __nv_bfloat16 h2 = __float2bfloat16(v2), h3 = __float2bfloat16(v3);
        __nv_bfloat16 l0 = __float2bfloat16(v0 - __bfloat162float(h0));
        __nv_bfloat16 l1 = __float2bfloat16(v1 - __bfloat162float(h1));
        __nv_bfloat16 l2 = __float2bfloat16(v2 - __bfloat162float(h2));
        __nv_bfloat16 l3 = __float2bfloat16(v3 - __bfloat162float(h3));
        uint4 r;
        r.x = ((uint32_t)__bfloat16_as_ushort(h1) << 16) | __bfloat16_as_ushort(h0);
        r.y = ((uint32_t)__bfloat16_as_ushort(h3) << 16) | __bfloat16_as_ushort(h2);
        r.z = ((uint32_t)__bfloat16_as_ushort(l1) << 16) | __bfloat16_as_ushort(l0);
        r.w = ((uint32_t)__bfloat16_as_ushort(l3) << 16) | __bfloat16_as_ushort(l2);
        Bfrag_g[c][t][lane] = r;
    }
    if (i < NL * 16 * DD * 12) {
        int e = i % 12;
        int r = i / 12;
        dwp_g[i] = (e < DD) ? dw[r * DD + e] : 0.0f;
    }
}

// ---------- helpers ----------
__device__ __forceinline__ void cvt_hilo(float vx, float vy, uint32_t &h, uint32_t &l) {
    asm("cvt.rn.bf16x2.f32 %0, %1, %2;" : "=r"(h) : "f"(vy), "f"(vx));
    float h0 = __uint_as_float(h << 16);
    float h1 = __uint_as_float(h & 0xffff0000u);
    float r0 = vx - h0, r1 = vy - h1;
    asm("cvt.rn.bf16x2.f32 %0, %1, %2;" : "=r"(l) : "f"(r1), "f"(r0));
}
__device__ __forceinline__ void mma16816(float* d, const uint32_t* a,
                                         uint32_t b0, uint32_t b1) {
    asm volatile(
        "mma.sync.aligned.m16n8k16.row.col.f32.bf16.bf16.f32 "
        "{%0,%1,%2,%3}, {%4,%5,%6,%7}, {%8,%9}, {%0,%1,%2,%3};"
        : "+f"(d[0]), "+f"(d[1]), "+f"(d[2]), "+f"(d[3])
        : "r"(a[0]), "r"(a[1]), "r"(a[2]), "r"(a[3]), "r"(b0), "r"(b1));
}
__device__ __forceinline__ void ffma2(ull &d, ull a, ull b) {
    asm("fma.rn.f32x2 %0, %1, %2, %0;" : "+l"(d) : "l"(a), "l"(b));
}
__device__ __forceinline__ ull pack2(float lo, float hi) {
    ull r; asm("mov.b64 %0, {%1, %2};" : "=l"(r) : "f"(lo), "f"(hi)); return r;
}
__device__ __forceinline__ void unpack2(ull v, float &lo, float &hi) {
    asm("mov.b64 {%0, %1}, %2;" : "=f"(lo), "=f"(hi) : "l"(v));
}

// ============================================================================
// Fused kernel: phase 1 (mma.sync bf16 3-pass hi/lo, k-permuted fragments so
// each thread's per-row A fragment = ONE float4 LDG) -> smem acts -> phase 2.
// ============================================================================
__global__ void __launch_bounds__(256, 2)
routenet_fused(const float* __restrict__ x,
               const float* __restrict__ bin,
               const float* __restrict__ gw,
               const float* __restrict__ db,
               const float* __restrict__ wout,
               float* __restrict__ out,
               int B)
{
    extern __shared__ __align__(16) float smf[];
    float* acts  = smf + SM_ACTS;
    float* gws   = smf + SM_GWS;
    float* dbs   = smf + SM_DBS;
    float* wouts = smf + SM_WOUTS;

    const int tid  = threadIdx.x;
    const int warp = tid >> 5;
    const int lane = tid & 31;
    const int qr   = lane >> 2;
    const int qc4  = (lane & 3) * 4;   // physical k base of this lane's fragment

    for (int i = tid; i < NL * 16 * DD; i += 256) { gws[i] = gw[i]; dbs[i] = db[i]; }
    for (int i = tid; i < WW * NOUT * DD; i += 256) wouts[i] = wout[i];

    // =====================================================================
    // Phase 1: warp covers 32 rows (2 m16 tiles) x 40 outputs (5 n8 tiles)
    // =====================================================================
    const int row0 = blockIdx.x * 256 + warp * 32;
    const float* xr = x + (size_t)row0 * NIN;

    float acc[2][5][4];
    #pragma unroll
    for (int mt = 0; mt < 2; ++mt)
        #pragma unroll
        for (int t = 0; t < 5; ++t)
            #pragma unroll
            for (int q = 0; q < 4; ++q) acc[mt][t][q] = 0.0f;

    #pragma unroll 1
    for (int c = 0; c < NKC; ++c) {
        const int k0 = c * 16 + qc4;

        uint32_t bh[5][2], bl[5][2];
        #pragma unroll
        for (int t = 0; t < 5; ++t) {
            uint4 bv = __ldg(&Bfrag_g[c][t][lane]);
            bh[t][0] = bv.x; bh[t][1] = bv.y;
            bl[t][0] = bv.z; bl[t][1] = bv.w;
        }

        // A fragments: ONE float4 per row (k-permuted); 2 rows per m-tile
        uint32_t ah[2][4], al[2][4];
        #pragma unroll
        for (int mt = 0; mt < 2; ++mt) {
            const float* pr = xr + (size_t)(mt * 16 + qr) * NIN + k0;
            float4 fa = *(const float4*)pr;              // row qr
            float4 fb = *(const float4*)(pr + 8 * NIN);  // row qr+8
            cvt_hilo(fa.x, fa.y, ah[mt][0], al[mt][0]);  // slots (2qc,2qc+1)   row qr
            cvt_hilo(fb.x, fb.y, ah[mt][1], al[mt][1]);  //                     row qr+8
            cvt_hilo(fa.z, fa.w, ah[mt][2], al[mt][2]);  // slots (2qc+8,2qc+9) row qr
            cvt_hilo(fb.z, fb.w, ah[mt][3], al[mt][3]);  //                     row qr+8
        }

        #pragma unroll
        for (int mt = 0; mt < 2; ++mt)
            #pragma unroll
            for (int t = 0; t < 5; ++t) {
                mma16816(acc[mt][t], ah[mt], bh[t][0], bh[t][1]);
                mma16816(acc[mt][t], al[mt], bh[t][0], bh[t][1]);
                mma16816(acc[mt][t], ah[mt], bl[t][0], bl[t][1]);
            }
    }

    // epilogue -> smem acts (block-local rows, stride ASTR)
    const int qc = (lane & 3) * 2;     // C-fragment columns (unpermuted)
    #pragma unroll
    for (int mt = 0; mt < 2; ++mt) {
        const int sra = warp * 32 + mt * 16 + qr;
        #pragma unroll
        for (int t = 0; t < 5; ++t) {
            const int cc = t * 8 + qc;
            float b0 = __ldg(bin + cc), b1 = __ldg(bin + cc + 1);
            float2 v0, v1;
            v0.x = fmaxf(acc[mt][t][0] + b0, 0.0f);
            v0.y = fmaxf(acc[mt][t][1] + b1, 0.0f);
            v1.x = fmaxf(acc[mt][t][2] + b0, 0.0f);
            v1.y = fmaxf(acc[mt][t][3] + b1, 0.0f);
            *(float2*)(acts + sra * ASTR + cc)       = v0;
            *(float2*)(acts + (sra + 8) * ASTR + cc) = v1;
        }
    }
    __syncthreads();

    // =====================================================================
    // Phase 2: one row per thread (row = blockIdx*256 + tid)
    // =====================================================================
    float a[WW][DD];
    {
        const float4* ap = (const float4*)(acts + tid * ASTR);
        #pragma unroll
        for (int i = 0; i < 10; ++i) {
            float4 v = ap[i];
            int o = i * 4;
            a[o / DD][o % DD]         = v.x;
            a[(o+1) / DD][(o+1) % DD] = v.y;
            a[(o+2) / DD][(o+2) % DD] = v.z;
            a[(o+3) / DD][(o+3) % DD] = v.w;
        }
    }

    float tg = 0.0f;

    #pragma unroll 1
    for (int l = 0; l < NL; ++l) {
        const float* gwl = gws + l * 160;
        const float* dbl = dbs + l * 160;
        const float* dwl = dwp_g + l * 16 * 120;

        ull nxt[WW][5];
        #pragma unroll
        for (int t = 0; t < WW; ++t)
            #pragma unroll
            for (int j = 0; j < 5; ++j) nxt[t][j] = 0ull;

        #pragma unroll
        for (int s = 0; s < WW; ++s) {
            ull a2[DD];
            #pragma unroll
            for (int d = 0; d < DD; ++d) a2[d] = pack2(a[s][d], a[s][d]);

            #pragma unroll
            for (int t = 0; t < WW; ++t) {
                const int edge = s * WW + t;

                const float* gv = gwl + edge * DD;
                float g = 0.0f;
                #pragma unroll
                for (int d = 0; d < DD; ++d) g += a[s][d] * gv[d];
                g = fminf(fmaxf(g, 0.0f), 1.0f);
                tg += g;
                ull g2 = pack2(g, g);

                ull m[5];
                const ull* bv = (const ull*)(dbl + edge * DD);
                #pragma unroll
                for (int j = 0; j < 5; ++j) m[j] = bv[j];

                const float* drow = dwl + edge * 120;
                #pragma unroll
                for (int din = 0; din < DD; ++din) {
                    const char* rp = (const char*)(drow + din * 12);
                    ulonglong2 wA = __ldg((const ulonglong2*)rp);
                    ulonglong2 wB = __ldg((const ulonglong2*)(rp + 16));
                    ull        wC = __ldg((const ull*)(rp + 32));
                    ull ad = a2[din];
                    ffma2(m[0], ad, wA.x);
                    ffma2(m[1], ad, wA.y);
                    ffma2(m[2], ad, wB.x);
                    ffma2(m[3], ad, wB.y);
                    ffma2(m[4], ad, wC);
                }

                #pragma unroll
                for (int j = 0; j < 5; ++j) ffma2(nxt[t][j], g2, m[j]);
            }
        }

        #pragma unroll
        for (int t = 0; t < WW; ++t)
            #pragma unroll
            for (int j = 0; j < 5; ++j) {
                float lo, hi; unpack2(nxt[t][j], lo, hi);
                a[t][2 * j]     = fmaxf(lo, 0.0f);
                a[t][2 * j + 1] = fmaxf(hi, 0.0f);
            }
    }

    // output banks + total_gate
    const size_t grow = (size_t)blockIdx.x * 256 + tid;
    float ov[NOUT];
    #pragma unroll
    for (int c = 0; c < NOUT; ++c) {
        float o = 0.0f;
        #pragma unroll
        for (int w = 0; w < WW; ++w)
            #pragma unroll
            for (int d = 0; d < DD; ++d)
                o += a[w][d] * wouts[(w * NOUT + c) * DD + d];
        ov[c] = o;
    }
    float2* op = (float2*)(out + grow * NOUT);
    #pragma unroll
    for (int j = 0; j < 5; ++j) op[j] = make_float2(ov[2 * j], ov[2 * j + 1]);
    out[(size_t)B * NOUT + grow] = tg;
}

extern "C" void kernel_launch(void* const* d_in, const int* in_sizes, int n_in,
                              void* d_out, int out_size)
{
    const float* x    = (const float*)d_in[0];
    const float* Win  = (const float*)d_in[1];
    const float* bin  = (const float*)d_in[2];
    const float* gw   = (const float*)d_in[3];
    const float* dw   = (const float*)d_in[4];
    const float* db   = (const float*)d_in[5];
    const float* wout = (const float*)d_in[6];

    const int B = in_sizes[0] / NIN;
    const int smem_bytes = SM_TOTF * 4;

    cudaFuncSetAttribute(routenet_fused,
                         cudaFuncAttributeMaxDynamicSharedMemorySize,
                         smem_bytes);

    prep_kernel<<<(NKC * 5 * 32 + 255) / 256, 256>>>(Win, dw);
    routenet_fused<<<B / 256, 256, smem_bytes>>>(x, bin, gw, db, wout,
                                                 (float*)d_out, B);
}